// round 1
// baseline (speedup 1.0000x reference)
#include <cuda_runtime.h>

#define DIM 1024
#define NPAIRS 512
#define THREADS 256   // 4 floats (2 pairs) per thread

// Composite complex butterfly coefficients, one per adjacent pair.
__device__ float2 g_coef[NPAIRS];

// W_j = prod_{l=1..9} (a_l - i b_l), where level-l params live at offset
// 4096 - 2^(12-l) and the block index for pair j is j >> (l-1).
__global__ void coef_kernel(const float* __restrict__ params) {
    int j = blockIdx.x * blockDim.x + threadIdx.x;
    if (j >= NPAIRS) return;
    float Wr = 1.0f, Wi = 0.0f;
#pragma unroll
    for (int l = 1; l <= 9; ++l) {
        int off = 4096 - (1 << (12 - l));
        int blk = j >> (l - 1);
        float a = params[off + 2 * blk];
        float b = params[off + 2 * blk + 1];
        // (Wr + i Wi) *= (a - i b)
        float nr = Wr * a + Wi * b;
        float ni = Wi * a - Wr * b;
        Wr = nr; Wi = ni;
    }
    g_coef[j] = make_float2(Wr, Wi);
}

__global__ __launch_bounds__(THREADS) void hyper_butterfly_kernel(
    const float4* __restrict__ x, float4* __restrict__ out)
{
    __shared__ float red1[8];
    __shared__ float red2[8];

    const int row = blockIdx.x;
    const int t   = threadIdx.x;
    const int lane = t & 31;
    const int wid  = t >> 5;

    // ---- load 4 elements (2 pairs) ----
    float4 v = __ldg(x + (size_t)row * (DIM / 4) + t);

    // ---- reduction 1: ||x||^2 ----
    float ss = v.x * v.x + v.y * v.y + v.z * v.z + v.w * v.w;
#pragma unroll
    for (int o = 16; o; o >>= 1) ss += __shfl_xor_sync(0xFFFFFFFFu, ss, o);
    if (lane == 0) red1[wid] = ss;
    __syncthreads();
    float n2 = red1[0] + red1[1] + red1[2] + red1[3]
             + red1[4] + red1[5] + red1[6] + red1[7];

    float n  = sqrtf(n2);
    float s1 = (n > 0.0f) ? (atanhf(n) / n) : 1.0f;   // log_map(0,x) scale

    // ---- butterfly: one complex multiply per adjacent pair ----
    // pairs 2t (wv.x,wv.y) and 2t+1 (wv.z,wv.w), contiguous -> one float4 load
    float4 wv = __ldg(((const float4*)g_coef) + t);
    float t0 = wv.x * v.x - wv.y * v.y;   // Re(W*z)
    float t1 = wv.y * v.x + wv.x * v.y;   // Im(W*z)
    float t2 = wv.z * v.z - wv.w * v.w;
    float t3 = wv.w * v.z + wv.z * v.w;

    // ---- reduction 2: ||W z||^2 (s1 factored out) ----
    float ss2 = t0 * t0 + t1 * t1 + t2 * t2 + t3 * t3;
#pragma unroll
    for (int o = 16; o; o >>= 1) ss2 += __shfl_xor_sync(0xFFFFFFFFu, ss2, o);
    if (lane == 0) red2[wid] = ss2;
    __syncthreads();
    float m2 = red2[0] + red2[1] + red2[2] + red2[3]
             + red2[4] + red2[5] + red2[6] + red2[7];

    float vn = s1 * sqrtf(m2);            // ||u||
    vn = fmaxf(vn, 1e-8f);
    float s2 = tanhf(vn) / vn;            // exp_map(0,u) scale
    float s  = s1 * s2;

    float4 o4 = make_float4(s * t0, s * t1, s * t2, s * t3);
    out[(size_t)row * (DIM / 4) + t] = o4;
}

extern "C" void kernel_launch(void* const* d_in, const int* in_sizes, int n_in,
                              void* d_out, int out_size) {
    // metadata order: x (32768*1024 floats), params (4092 floats).
    // Defensive: identify params by its small size.
    const float* xp = (const float*)d_in[0];
    const float* pp = (const float*)d_in[1];
    long long n0 = in_sizes[0], n1 = in_sizes[1];
    if (n0 < n1) { const float* tmp = xp; xp = pp; pp = tmp; long long ts = n0; n0 = n1; n1 = ts; }
    int rows = (int)(n0 / DIM);

    coef_kernel<<<1, NPAIRS>>>(pp);
    hyper_butterfly_kernel<<<rows, THREADS>>>((const float4*)xp, (float4*)d_out);
}

// round 2
// speedup vs baseline: 1.3973x; 1.3973x over previous
#include <cuda_runtime.h>

#define DIM 1024
#define NPAIRS 512
#define THREADS 128   // 8 floats (4 pairs) per thread, one row per block

// Composite complex butterfly coefficients, one per adjacent pair.
__device__ float2 g_coef[NPAIRS];

// W_j = prod_{l=1..9} (a_l - i b_l); level-l params at offset 4096 - 2^(12-l),
// block index for pair j is j >> (l-1).
__global__ void coef_kernel(const float* __restrict__ params) {
    int j = blockIdx.x * blockDim.x + threadIdx.x;
    if (j >= NPAIRS) return;
    float Wr = 1.0f, Wi = 0.0f;
#pragma unroll
    for (int l = 1; l <= 9; ++l) {
        int off = 4096 - (1 << (12 - l));
        int blk = j >> (l - 1);
        float a = params[off + 2 * blk];
        float b = params[off + 2 * blk + 1];
        float nr = Wr * a + Wi * b;     // (Wr + i Wi) *= (a - i b)
        float ni = Wi * a - Wr * b;
        Wr = nr; Wi = ni;
    }
    g_coef[j] = make_float2(Wr, Wi);
}

__global__ __launch_bounds__(THREADS) void hyper_butterfly_kernel(
    const float4* __restrict__ x, float4* __restrict__ out)
{
    __shared__ float red[8];   // [0..3] = ss per warp, [4..7] = ss2 per warp

    const int row  = blockIdx.x;
    const int t    = threadIdx.x;
    const int lane = t & 31;
    const int wid  = t >> 5;

    const size_t base = (size_t)row * (DIM / 4);

    // ---- load 8 elements (two coalesced float4 loads, MLP=2) ----
    float4 v0 = __ldg(x + base + t);
    float4 v1 = __ldg(x + base + THREADS + t);

    // coefficient loads (L2/L1 resident, 4 KB table)
    float4 w0 = __ldg(((const float4*)g_coef) + t);
    float4 w1 = __ldg(((const float4*)g_coef) + THREADS + t);

    // ---- ||x||^2 partial ----
    float ss = v0.x * v0.x + v0.y * v0.y + v0.z * v0.z + v0.w * v0.w
             + v1.x * v1.x + v1.y * v1.y + v1.z * v1.z + v1.w * v1.w;

    // ---- butterfly: complex multiply per adjacent pair (independent of s1) ----
    float a0 = w0.x * v0.x - w0.y * v0.y;
    float a1 = w0.y * v0.x + w0.x * v0.y;
    float a2 = w0.z * v0.z - w0.w * v0.w;
    float a3 = w0.w * v0.z + w0.z * v0.w;
    float b0 = w1.x * v1.x - w1.y * v1.y;
    float b1 = w1.y * v1.x + w1.x * v1.y;
    float b2 = w1.z * v1.z - w1.w * v1.w;
    float b3 = w1.w * v1.z + w1.z * v1.w;

    // ---- ||W z||^2 partial ----
    float ss2 = a0 * a0 + a1 * a1 + a2 * a2 + a3 * a3
              + b0 * b0 + b1 * b1 + b2 * b2 + b3 * b3;

    // ---- single fused reduction: two interleaved shuffle trees ----
#pragma unroll
    for (int o = 16; o; o >>= 1) {
        ss  += __shfl_xor_sync(0xFFFFFFFFu, ss,  o);
        ss2 += __shfl_xor_sync(0xFFFFFFFFu, ss2, o);
    }
    if (lane == 0) { red[wid] = ss; red[4 + wid] = ss2; }
    __syncthreads();

    float n2 = red[0] + red[1] + red[2] + red[3];
    float m2 = red[4] + red[5] + red[6] + red[7];

    // log_map(0,x) scale: atanh(||x||)/||x||
    float n  = sqrtf(n2);
    float s1 = (n > 0.0f) ? (atanhf(n) / n) : 1.0f;

    // exp_map(0,u) scale with u = s1 * (W z): ||u|| = s1 * sqrt(m2)
    float vn = s1 * sqrtf(m2);
    vn = fmaxf(vn, 1e-8f);
    float s = s1 * (tanhf(vn) / vn);

    // ---- scale & store ----
    out[base + t]           = make_float4(s * a0, s * a1, s * a2, s * a3);
    out[base + THREADS + t] = make_float4(s * b0, s * b1, s * b2, s * b3);
}

extern "C" void kernel_launch(void* const* d_in, const int* in_sizes, int n_in,
                              void* d_out, int out_size) {
    const float* xp = (const float*)d_in[0];
    const float* pp = (const float*)d_in[1];
    long long n0 = in_sizes[0], n1 = in_sizes[1];
    if (n0 < n1) { const float* tmp = xp; xp = pp; pp = tmp; long long ts = n0; n0 = n1; n1 = ts; }
    int rows = (int)(n0 / DIM);

    coef_kernel<<<1, NPAIRS>>>(pp);
    hyper_butterfly_kernel<<<rows, THREADS>>>((const float4*)xp, (float4*)d_out);
}